// round 8
// baseline (speedup 1.0000x reference)
#include <cuda_runtime.h>

#define EPS 1e-5f

typedef unsigned long long ull;

// ---------------- scratch (static device memory; no allocations) ----------------
static __device__ __align__(16) float g_x2[128 * 64 * 3136];       // 102.8 MB: x * attn
static __device__ __align__(16) float g_gate[2 * 16 * 8 * 3136];   // 3.2 MB : tanh(conv3d)
static __device__ float g_psum[64 * 1024];                         // BN partial sums
static __device__ float g_psq[64 * 1024];                          // BN partial sumsq
static __device__ float g_scale[64];
static __device__ float g_bias[64];

// ---------------- helpers ----------------
__device__ __forceinline__ ull pack2(float a, float b) {
    ull r;
    asm("mov.b64 %0, {%1, %2};" : "=l"(r) : "r"(__float_as_uint(a)), "r"(__float_as_uint(b)));
    return r;
}
__device__ __forceinline__ void unpack2(ull v, float& a, float& b) {
    unsigned int ua, ub;
    asm("mov.b64 {%0, %1}, %2;" : "=r"(ua), "=r"(ub) : "l"(v));
    a = __uint_as_float(ua);
    b = __uint_as_float(ub);
}
__device__ __forceinline__ ull fma2(ull a, ull b, ull c) {
    ull d;
    asm("fma.rn.f32x2 %0, %1, %2, %3;" : "=l"(d) : "l"(a), "l"(b), "l"(c));
    return d;
}
// R2-proven accurate forms. MUFU.TANH / expf-composed tanh both FAILED the 1e-3
// threshold (R3: 2.7e-3, R4: 3.9e-3) — do not substitute.
__device__ __forceinline__ float sigmoid_exact(float x) {
    return 1.f / (1.f + __expf(-x));
}

#define CH_STRIDE 1088  // 16*68 floats per channel (kernelC tile)

__global__ void kNop() {}

// =====================================================================
// Kernel A: attn conv2d (4 heads, 3x3, C=64) -> sigmoid(relu(.)),
//           x2 = x * attn, BN partial sums.
// BARRIER-FREE mainloop: data via direct LDG (L1-resident working set),
// weights in smem (broadcast). grid (128, 8) = 7-row tiles, block 128,
// 98 compute threads (1h x 4w each), heads packed as 2 f32x2 pairs.
// =====================================================================
__global__ void __launch_bounds__(128) kernelA(const float* __restrict__ x,
                                               const float* __restrict__ attn_w,
                                               const float* __restrict__ attn_b) {
    __shared__ __align__(16) ull s_w[64][9][2];
    __shared__ __align__(16) float s_attn[4][392];

    const int n = blockIdx.x;
    const int h_base = blockIdx.y * 7;
    const int tid = threadIdx.x;

    for (int i = tid; i < 576; i += 128) {
        int c = i / 9, k = i - c * 9;
        s_w[c][k][0] = pack2(attn_w[c * 9 + k], attn_w[576 + c * 9 + k]);
        s_w[c][k][1] = pack2(attn_w[1152 + c * 9 + k], attn_w[1728 + c * 9 + k]);
    }
    __syncthreads();  // the ONLY pre-mainloop barrier (weights ready)

    const bool active = tid < 98;
    const int hi = tid / 14, wi = tid - hi * 14;
    const int oh = h_base + hi;   // 0..55
    const int w0 = 4 * wi;
    const bool hasL = (wi != 0), hasR = (wi != 13);
    const float* xn = x + n * 200704;

    ull acc[4][2];
#pragma unroll
    for (int p = 0; p < 4; p++) { acc[p][0] = 0ull; acc[p][1] = 0ull; }

    if (active) {
        const bool rok0 = (oh >= 1), rok2 = (oh <= 54);
        const float* rowbase = xn + (oh - 1) * 56 + w0;
#pragma unroll 2
        for (int c = 0; c < 64; c++) {
            const float* cb = rowbase + c * 3136;
#pragma unroll
            for (int r = 0; r < 3; r++) {
                if (r == 0 && !rok0) continue;
                if (r == 2 && !rok2) continue;
                const float* rp = cb + r * 56;
                float4 q = *(const float4*)rp;
                float vl = hasL ? rp[-1] : 0.f;
                float vr = hasR ? rp[4] : 0.f;
                ull p0 = pack2(vl, vl), p1 = pack2(q.x, q.x), p2 = pack2(q.y, q.y);
                ull p3 = pack2(q.z, q.z), p4 = pack2(q.w, q.w), p5 = pack2(vr, vr);
                ull wl, wh;
                wl = s_w[c][r * 3 + 0][0]; wh = s_w[c][r * 3 + 0][1];
                acc[0][0] = fma2(p0, wl, acc[0][0]); acc[1][0] = fma2(p1, wl, acc[1][0]);
                acc[2][0] = fma2(p2, wl, acc[2][0]); acc[3][0] = fma2(p3, wl, acc[3][0]);
                acc[0][1] = fma2(p0, wh, acc[0][1]); acc[1][1] = fma2(p1, wh, acc[1][1]);
                acc[2][1] = fma2(p2, wh, acc[2][1]); acc[3][1] = fma2(p3, wh, acc[3][1]);
                wl = s_w[c][r * 3 + 1][0]; wh = s_w[c][r * 3 + 1][1];
                acc[0][0] = fma2(p1, wl, acc[0][0]); acc[1][0] = fma2(p2, wl, acc[1][0]);
                acc[2][0] = fma2(p3, wl, acc[2][0]); acc[3][0] = fma2(p4, wl, acc[3][0]);
                acc[0][1] = fma2(p1, wh, acc[0][1]); acc[1][1] = fma2(p2, wh, acc[1][1]);
                acc[2][1] = fma2(p3, wh, acc[2][1]); acc[3][1] = fma2(p4, wh, acc[3][1]);
                wl = s_w[c][r * 3 + 2][0]; wh = s_w[c][r * 3 + 2][1];
                acc[0][0] = fma2(p2, wl, acc[0][0]); acc[1][0] = fma2(p3, wl, acc[1][0]);
                acc[2][0] = fma2(p4, wl, acc[2][0]); acc[3][0] = fma2(p5, wl, acc[3][0]);
                acc[0][1] = fma2(p2, wh, acc[0][1]); acc[1][1] = fma2(p3, wh, acc[1][1]);
                acc[2][1] = fma2(p4, wh, acc[2][1]); acc[3][1] = fma2(p5, wh, acc[3][1]);
            }
        }
        float b0 = attn_b[0], b1 = attn_b[1], b2 = attn_b[2], b3v = attn_b[3];
#pragma unroll
        for (int p = 0; p < 4; p++) {
            float a0, a1, a2, a3;
            unpack2(acc[p][0], a0, a1);
            unpack2(acc[p][1], a2, a3);
            a0 = fmaxf(a0 + b0, 0.f);
            a1 = fmaxf(a1 + b1, 0.f);
            a2 = fmaxf(a2 + b2, 0.f);
            a3 = fmaxf(a3 + b3v, 0.f);
            int px = hi * 56 + w0 + p;
            s_attn[0][px] = sigmoid_exact(a0);
            s_attn[1][px] = sigmoid_exact(a1);
            s_attn[2][px] = sigmoid_exact(a2);
            s_attn[3][px] = sigmoid_exact(a3);
        }
    }
    __syncthreads();

    // phase 2: x2 = x * attn, BN partial sums (x rows are L1-hot from mainloop)
    const int warp = tid >> 5, lane = tid & 31;
    const int pidx = n * 8 + blockIdx.y;  // 0..1023
    for (int c = warp; c < 64; c += 4) {
        int head = c >> 4;
        const float4* xp = (const float4*)(xn + c * 3136 + h_base * 56);
        float4* x2p = (float4*)(g_x2 + n * 200704 + c * 3136 + h_base * 56);
        const float4* ap = (const float4*)&s_attn[head][0];
        float sum = 0.f, sq = 0.f;
        for (int i = lane; i < 98; i += 32) {
            float4 xv = xp[i], av = ap[i];
            float4 v;
            v.x = xv.x * av.x;
            v.y = xv.y * av.y;
            v.z = xv.z * av.z;
            v.w = xv.w * av.w;
            x2p[i] = v;
            sum += (v.x + v.y) + (v.z + v.w);
            sq += (v.x * v.x + v.y * v.y) + (v.z * v.z + v.w * v.w);
        }
#pragma unroll
        for (int o = 16; o; o >>= 1) {
            sum += __shfl_down_sync(0xffffffffu, sum, o);
            sq += __shfl_down_sync(0xffffffffu, sq, o);
        }
        if (lane == 0) {
            g_psum[c * 1024 + pidx] = sum;
            g_psq[c * 1024 + pidx] = sq;
        }
    }
}

// =====================================================================
// Kernel B: reduce BN partials -> per-channel scale/bias. grid 64, block 32.
// =====================================================================
__global__ void kernelB(const float* __restrict__ gamma, const float* __restrict__ beta) {
    int c = blockIdx.x, lane = threadIdx.x;
    float s = 0.f, q = 0.f;
    for (int i = lane; i < 1024; i += 32) {
        s += g_psum[c * 1024 + i];
        q += g_psq[c * 1024 + i];
    }
#pragma unroll
    for (int o = 16; o; o >>= 1) {
        s += __shfl_down_sync(0xffffffffu, s, o);
        q += __shfl_down_sync(0xffffffffu, q, o);
    }
    if (lane == 0) {
        const float inv_n = 1.f / 401408.f;
        float mean = s * inv_n;
        float var = q * inv_n - mean * mean;
        float sc = gamma[c] * rsqrtf(var + EPS);
        g_scale[c] = sc;
        g_bias[c] = beta[c] - mean * sc;
    }
}

// ---------------- one t-pair conv contribution (3x3 over 4 channels) ----------------
__device__ __forceinline__ void conv_pair(const float* tb, const ull(*wt)[9],
                                          int hi, int wi, ull* acc) {
#pragma unroll
    for (int cc = 0; cc < 4; cc++) {
        const ull* wv = wt[cc];
#pragma unroll
        for (int r = 0; r < 3; r++) {
            const float* rp = tb + cc * CH_STRIDE + (hi + r) * 68 + 4 + 4 * wi;
            float4 q = *(const float4*)rp;
            float vl = rp[-1], vr = rp[4];
            ull p0 = pack2(vl, vl), p1 = pack2(q.x, q.x), p2 = pack2(q.y, q.y);
            ull p3 = pack2(q.z, q.z), p4 = pack2(q.w, q.w), p5 = pack2(vr, vr);
            ull w;
            w = wv[r * 3 + 0];
            acc[0] = fma2(p0, w, acc[0]); acc[1] = fma2(p1, w, acc[1]);
            acc[2] = fma2(p2, w, acc[2]); acc[3] = fma2(p3, w, acc[3]);
            w = wv[r * 3 + 1];
            acc[0] = fma2(p1, w, acc[0]); acc[1] = fma2(p2, w, acc[1]);
            acc[2] = fma2(p3, w, acc[2]); acc[3] = fma2(p4, w, acc[3]);
            w = wv[r * 3 + 2];
            acc[0] = fma2(p2, w, acc[0]); acc[1] = fma2(p3, w, acc[1]);
            acc[2] = fma2(p4, w, acc[2]); acc[3] = fma2(p5, w, acc[3]);
        }
    }
}

// =====================================================================
// Kernel C: grouped conv3d (3x3x3, 32ch -> 1 per group) on relu(bn(x2)),
//           tanh -> g_gate. t-PAIR blocks (2 output t's packed per f32x2):
// grid (64 [b*4+pair], 2 g, 4 htile) = 512 blocks; block 224, 196 active.
// =====================================================================
__global__ void __launch_bounds__(224) kernelC(const float* __restrict__ w3,
                                               const float* __restrict__ b3) {
    __shared__ __align__(16) ull s_wp[4][32][9];  // [i][c][tap] = (W(i), W(i-1))
    __shared__ __align__(16) float s_tile[2][4][16][68];
    __shared__ float s_sc[32], s_bi[32];

    const int bx = blockIdx.x;          // 0..63
    const int b = bx >> 2;
    const int t0 = (bx & 3) * 2;        // pair base: 0,2,4,6
    const int g = blockIdx.y;
    const int h_base = blockIdx.z * 14;
    const int tid = threadIdx.x;

    for (int i = tid; i < 288; i += 224) {
        int c = i / 9, k = i - c * 9;
        float w0v = w3[g * 864 + c * 27 + k];
        float w1v = w3[g * 864 + c * 27 + 9 + k];
        float w2v = w3[g * 864 + c * 27 + 18 + k];
        s_wp[0][c][k] = pack2(w0v, 0.f);
        s_wp[1][c][k] = pack2(w1v, w0v);
        s_wp[2][c][k] = pack2(w2v, w1v);
        s_wp[3][c][k] = pack2(0.f, w2v);
    }
    if (tid < 32) {
        s_sc[tid] = g_scale[g * 32 + tid];
        s_bi[tid] = g_bias[g * 32 + tid];
    }
    // pre-zero always-zero halo columns of both buffers (disjoint from STS cells)
    for (int i = tid; i < 2 * 4 * 16; i += 224) {
        int buf = i >> 6, rem = i & 63;
        float* row = &s_tile[buf][rem >> 4][rem & 15][0];
        row[3] = 0.f;
        row[60] = 0.f;
    }
    // CRITICAL: stage-0 tile-write reads s_sc/s_bi (written by warp 0 only)
    // BEFORE the in-loop barrier — this barrier orders init vs those reads
    // (its absence was the R3-R5 1.7e-3 error).
    __syncthreads();

    // per-thread load slot
    const int lr = tid / 14, cg = tid - lr * 14;
    const int gh = h_base - 1 + lr;
    const bool lvalid = (unsigned)gh < 56u;
    const int goff = gh * 56 + cg * 4;
    const int soff = lr * 68 + 4 + cg * 4;

    // slice window: i = ts - (t0-1); slice contributes W(i) to t0, W(i-1) to t0+1
    const int i_lo = (t0 == 0) ? 1 : 0;
    const int i_hi = (t0 == 6) ? 2 : 3;
    const int nst = (i_hi - i_lo + 1) * 8;  // 24 or 32 stages

    const float4 z4 = make_float4(0.f, 0.f, 0.f, 0.f);
    float4 st[4];
    {
        int ts = t0 - 1 + i_lo;
        const float* src = g_x2 + ((b * 8 + ts) * 64 + g * 32) * 3136 + goff;
#pragma unroll
        for (int cc = 0; cc < 4; cc++)
            st[cc] = lvalid ? *(const float4*)(src + cc * 3136) : z4;
    }

    const bool active = tid < 196;
    const int hi = tid / 14, wi = tid - hi * 14;

    ull acc[4] = {0ull, 0ull, 0ull, 0ull};  // (t0, t0+1) per pixel

    for (int s = 0; s < nst; s++) {
        const int i_sl = i_lo + (s >> 3);
        const int c0 = (s & 7) * 4;
        float* tb = &s_tile[s & 1][0][0][0];
#pragma unroll
        for (int cc = 0; cc < 4; cc++) {
            float sc = s_sc[c0 + cc], bi = s_bi[c0 + cc];
            float4 v;
            if (lvalid) {
                v.x = fmaxf(fmaf(st[cc].x, sc, bi), 0.f);
                v.y = fmaxf(fmaf(st[cc].y, sc, bi), 0.f);
                v.z = fmaxf(fmaf(st[cc].z, sc, bi), 0.f);
                v.w = fmaxf(fmaf(st[cc].w, sc, bi), 0.f);
            } else {
                v = z4;  // spatial zero-pad AFTER bn+relu
            }
            *(float4*)(tb + cc * CH_STRIDE + soff) = v;
        }
        __syncthreads();
        if (s + 1 < nst) {
            int i_n = i_lo + ((s + 1) >> 3);
            int tsn = t0 - 1 + i_n;
            int c0n = ((s + 1) & 7) * 4;
            const float* src = g_x2 + ((b * 8 + tsn) * 64 + g * 32 + c0n) * 3136 + goff;
#pragma unroll
            for (int cc = 0; cc < 4; cc++)
                st[cc] = lvalid ? *(const float4*)(src + cc * 3136) : z4;
        }
        if (active) conv_pair(tb, &s_wp[i_sl][c0], hi, wi, acc);
    }

    if (active) {
        float cb = b3[g];
        int hw = (h_base + hi) * 56 + 4 * wi;
        float* gp = g_gate + ((g * 16 + b) * 8 + t0) * 3136 + hw;
#pragma unroll
        for (int p = 0; p < 4; p++) {
            float o0, o1;
            unpack2(acc[p], o0, o1);
            gp[p] = tanhf(o0 + cb);
            gp[3136 + p] = tanhf(o1 + cb);
        }
    }
}

// =====================================================================
// Kernel D: gate apply + temporal shift + channel interleave, float4 streaming.
// =====================================================================
__global__ void __launch_bounds__(256) kernelD(float* __restrict__ out) {
    int idx = blockIdx.x * 256 + threadIdx.x;
    int w4 = idx % 14;
    int tmp = idx / 14;
    int h = tmp % 56;
    tmp /= 56;
    int c_out = tmp & 63;
    int b = tmp >> 6;

    int gsel = c_out >> 5;
    int cc = c_out & 31;
    int c_src = gsel * 32 + (cc & 1) * 16 + (cc >> 1);

    int hw = h * 56 + w4 * 4;
    const float4* gbase = (const float4*)(g_gate + ((gsel * 16 + b) * 8) * 3136 + hw);
    int xoff0 = (b * 8) * 64 * 3136 + c_src * 3136 + hw;
    int ooff0 = (b * 8) * 64 * 3136 + c_out * 3136 + hw;

    float4 py = make_float4(0.f, 0.f, 0.f, 0.f);
    if (gsel == 0) {
#pragma unroll
        for (int t = 7; t >= 0; --t) {
            float4 xt = *(const float4*)(g_x2 + xoff0 + t * 64 * 3136);
            float4 gt = gbase[t * 784];
            float4 o;
            o.x = py.x + (1.f - gt.x) * xt.x;
            o.y = py.y + (1.f - gt.y) * xt.y;
            o.z = py.z + (1.f - gt.z) * xt.z;
            o.w = py.w + (1.f - gt.w) * xt.w;
            *(float4*)(out + ooff0 + t * 64 * 3136) = o;
            py.x = gt.x * xt.x;
            py.y = gt.y * xt.y;
            py.z = gt.z * xt.z;
            py.w = gt.w * xt.w;
        }
    } else {
#pragma unroll
        for (int t = 0; t < 8; ++t) {
            float4 xt = *(const float4*)(g_x2 + xoff0 + t * 64 * 3136);
            float4 gt = gbase[t * 784];
            float4 o;
            o.x = py.x + (1.f - gt.x) * xt.x;
            o.y = py.y + (1.f - gt.y) * xt.y;
            o.z = py.z + (1.f - gt.z) * xt.z;
            o.w = py.w + (1.f - gt.w) * xt.w;
            *(float4*)(out + ooff0 + t * 64 * 3136) = o;
            py.x = gt.x * xt.x;
            py.y = gt.y * xt.y;
            py.z = gt.z * xt.z;
            py.w = gt.w * xt.w;
        }
    }
}

// =====================================================================
extern "C" void kernel_launch(void* const* d_in, const int* in_sizes, int n_in,
                              void* d_out, int out_size) {
    const float* x = (const float*)d_in[0];
    const float* attn_w = (const float*)d_in[1];
    const float* attn_b = (const float*)d_in[2];
    const float* gamma = (const float*)d_in[3];
    const float* beta = (const float*)d_in[4];
    const float* w3 = (const float*)d_in[5];
    const float* b3 = (const float*)d_in[6];
    float* out = (float*)d_out;

    // 1 nop: shifts kernelC into ncu's captured slot (#6 = h1,h2,nop,A,B,C)
    kNop<<<1, 32>>>();
    kernelA<<<dim3(128, 8), 128>>>(x, attn_w, attn_b);
    kernelB<<<64, 32>>>(gamma, beta);
    kernelC<<<dim3(64, 2, 4), 224>>>(w3, b3);
    kernelD<<<3136, 256>>>(out);
}